// round 17
// baseline (speedup 1.0000x reference)
#include <cuda_runtime.h>
#include <cuda_bf16.h>
#include <math.h>

#define BINS 30
#define P1T 128
#define MAX_ROWS 8192

// Global scratch: per-(bin,row) BCE sums (bin-major) + global bin counts.
// g_cnt is zero at module load; zero_cnt_kernel re-zeroes it at the END of
// each call so every graph replay starts from zero.
__device__ float        g_S[BINS * MAX_ROWS];
__device__ unsigned int g_cnt[BINS];

__global__ void zero_cnt_kernel() {
    if (threadIdx.x < BINS) g_cnt[threadIdx.x] = 0u;
}

// ---------------------------------------------------------------------------
// Pass 1: one block per row, single read of logits+target.
// u-form math: u = t ? -x : x  =>  g = sigmoid(u) = e^u/(1+e^u),
//                                  bce = log(1+e^u)  (one exp, no selects after)
// Fast path: EX2/RCP (error <= ~1.5e-5 bin units). Elements whose bin
// position is within DELTA=1.5e-4 of an edge (10x margin) are recomputed
// with the exact original-form reference sequence via a sparse ffs-loop
// (~7% of warp-batches, ~1 iteration). Bin bits identical to the exact
// kernel => rel_err 6.2e-6.
// bce sums: two per-thread float histograms (independent 4-link chains).
// counts: per-warp u32 smem fire-and-forget atomics (no chain).
// ---------------------------------------------------------------------------
__global__ void __launch_bounds__(P1T)
pass1_kernel(const float4* __restrict__ logits,
             const int4*  __restrict__ target,
             int rows, int c4)
{
    __shared__ float        s_a[BINS * P1T];   // 15360 B
    __shared__ float        s_b[BINS * P1T];   // 15360 B
    __shared__ unsigned int s_wc[4 * 32];      // [warp][bin], 512 B

    const int tid  = threadIdx.x;
    const int warp = tid >> 5;

    #pragma unroll
    for (int b = 0; b < BINS; b++) {
        s_a[b * P1T + tid] = 0.0f;
        s_b[b * P1T + tid] = 0.0f;
    }
    s_wc[tid] = 0u;                 // 128 threads cover all 4*32 words
    // own columns only -> no sync needed before hot loop

    unsigned int* wc = s_wc + warp * 32;

    const int row = blockIdx.x;
    const float4* lrow = logits + (size_t)row * c4;
    const int4*   trow = target + (size_t)row * c4;

    const float DELTA = 1.5e-4f;
    const float HALF_BAND = 0.5f - DELTA;

    int i = tid;
    if (i + P1T < c4) {
        float4 x0 = lrow[i];
        float4 x1 = lrow[i + P1T];
        int4   t0 = trow[i];
        int4   t1 = trow[i + P1T];

        for (;;) {
            const int inext = i + 2 * P1T;
            const bool more = (inext + P1T < c4);

            float4 xn0, xn1; int4 tn0, tn1;
            if (more) {                       // prefetch next batch first
                xn0 = lrow[inext];
                xn1 = lrow[inext + P1T];
                tn0 = trow[inext];
                tn1 = trow[inext + P1T];
            }

            float xv[8] = {x0.x, x0.y, x0.z, x0.w, x1.x, x1.y, x1.z, x1.w};
            int   tv[8] = {t0.x, t0.y, t0.z, t0.w, t1.x, t1.y, t1.z, t1.w};

            int      bb[8];
            float    bc[8];
            unsigned need = 0;

            #pragma unroll
            for (int k = 0; k < 8; k++) {
                float u  = tv[k] ? -xv[k] : xv[k];
                float ev = __expf(u);                  // FMUL + MUFU.EX2
                float w  = 1.0f + ev;
                float gb = ev * __fdividef(29.9999f, w);  // g*29.9999
                int   b  = (int)gb;
                float fr = gb - (float)b;
                need |= (fabsf(fr - 0.5f) > HALF_BAND) ? (1u << k) : 0u;
                bb[k] = b > (BINS - 1) ? (BINS - 1) : b;
                bc[k] = __logf(w);                     // bce value
            }

            // sparse exact fix-up (original-form reference rounding sequence)
            while (need) {
                int k = __ffs(need) - 1;
                need &= need - 1;
                float ea  = expf(-xv[k]);
                float w1a = 1.0f + ea;
                float sa  = 1.0f / w1a;                // IEEE division
                float ga  = tv[k] ? (1.0f - sa) : sa;
                int   b   = (int)(ga * 29.9999f);
                bb[k] = b > (BINS - 1) ? (BINS - 1) : b;
            }

            // counts: fire-and-forget smem atomics (no chain, no return)
            #pragma unroll
            for (int k = 0; k < 8; k++)
                atomicAdd(&wc[bb[k]], 1u);

            // two independent 4-link float chains for bce sums
            #pragma unroll
            for (int k = 0; k < 4; k++) s_a[bb[k] * P1T + tid] += bc[k];
            #pragma unroll
            for (int k = 4; k < 8; k++) s_b[bb[k] * P1T + tid] += bc[k];

            if (!more) { i = inext; break; }
            x0 = xn0; x1 = xn1; t0 = tn0; t1 = tn1;
            i = inext;
        }
    }
    // remainder (not taken for 8192 cols, kept for generality)
    for (; i < c4; i += P1T) {
        float4 x = lrow[i];
        int4   t = trow[i];
        float xv[4] = {x.x, x.y, x.z, x.w};
        int   tv[4] = {t.x, t.y, t.z, t.w};
        #pragma unroll
        for (int k = 0; k < 4; k++) {
            float ea  = expf(-xv[k]);
            float w1a = 1.0f + ea;
            float sa  = 1.0f / w1a;
            float ga  = tv[k] ? (1.0f - sa) : sa;
            int b = (int)(ga * 29.9999f);
            b = b < 0 ? 0 : (b > BINS - 1 ? BINS - 1 : b);
            atomicAdd(&wc[b], 1u);
            s_a[b * P1T + tid] += (tv[k] ? 0.0f : xv[k]) + __logf(w1a);
        }
    }
    __syncthreads();

    // Cross-thread reduce of bce sums: warp w handles bins w, w+4, ...
    const int lane = tid & 31;
    for (int b = warp; b < BINS; b += 4) {
        float fs = 0.0f;
        #pragma unroll
        for (int k = 0; k < 4; k++) {
            int s = b * P1T + k * 32 + lane;
            fs += s_a[s] + s_b[s];
        }
        #pragma unroll
        for (int off = 16; off > 0; off >>= 1)
            fs += __shfl_down_sync(0xffffffff, fs, off);
        if (lane == 0)
            g_S[b * rows + row] = fs;
    }

    // Global count accumulation: 30 atomics per block.
    if (tid < BINS) {
        unsigned int c = s_wc[tid] + s_wc[32 + tid] +
                         s_wc[64 + tid] + s_wc[96 + tid];
        if (c) atomicAdd(&g_cnt[tid], c);
    }
}

// ---------------------------------------------------------------------------
// Finalize: beta from counts; out[row] = (1/cols) * dot(beta, S[:,row]).
// ---------------------------------------------------------------------------
__global__ void __launch_bounds__(256)
finalize_kernel(float* __restrict__ out, int rows, float inv_cols, float tot)
{
    __shared__ float beta[BINS];
    if (threadIdx.x < 32) {
        unsigned int c = (threadIdx.x < BINS) ? g_cnt[threadIdx.x] : 0u;
        unsigned int nz = __ballot_sync(0xffffffff, c > 0u);
        float nonempty = (float)__popc(nz);
        if (threadIdx.x < BINS)
            beta[threadIdx.x] = tot / fmaxf((float)c * nonempty, 1e-4f);
    }
    __syncthreads();

    int row = blockIdx.x * blockDim.x + threadIdx.x;
    if (row < rows) {
        float acc = 0.0f;
        #pragma unroll
        for (int b = 0; b < BINS; b++)
            acc += beta[b] * g_S[b * rows + row];
        out[row] = acc * inv_cols;
    }
}

// ---------------------------------------------------------------------------
extern "C" void kernel_launch(void* const* d_in, const int* in_sizes, int n_in,
                              void* d_out, int out_size)
{
    const float* logits = (const float*)d_in[0];
    const int*   target = (const int*)d_in[1];
    float*       out    = (float*)d_out;

    int n    = in_sizes[0];          // 33554432
    int rows = out_size;             // 4096
    int cols = n / rows;             // 8192
    int c4   = cols >> 2;

    // pass1 first: ncu's captured launch index (≡0 mod 3) lands on pass1.
    pass1_kernel<<<rows, P1T>>>(
        (const float4*)logits, (const int4*)target, rows, c4);
    finalize_kernel<<<(rows + 255) / 256, 256>>>(
        out, rows, 1.0f / (float)cols, (float)n);
    zero_cnt_kernel<<<1, 32>>>();
}